// round 15
// baseline (speedup 1.0000x reference)
#include <cuda_runtime.h>
#include <cstdint>

typedef unsigned long long u64;

#define HD   19      // hidden size
#define HJ   20      // padded row stride
#define DD   64      // input size
#define TPB  128
#define RPT  2       // batch rows per thread (packed in f32x2 lanes)
#define RPB  (TPB * RPT)
#define NPART 1024

__device__ float g_partials[NPART];

struct CTab {                 // all weights pre-duplicated (w,w) as u64
    u64 Wi2[DD * HJ];         // [k][j] = dup(Wi[j][k])
    u64 Wr2[HD * HJ];
    u64 Wo2[HD * HJ];
    u64 bi2[HJ];
    u64 bo2[HJ];
    u64 bdt2[HJ];             // dup(dt / tau_dyn)
};
__device__ CTab g_ctab;       // staging, written by k_prep
__constant__ CTab c_tab;      // uniform-path weights for k_main
#define CTAB_U64 ((int)(sizeof(CTab) / 8))

// ---------- packed f32x2 helpers ----------
static __device__ __forceinline__ u64 pk2(float lo, float hi) {
    u64 r; asm("mov.b64 %0,{%1,%2};" : "=l"(r) : "f"(lo), "f"(hi)); return r;
}
static __device__ __forceinline__ void upk2(u64 v, float& lo, float& hi) {
    asm("mov.b64 {%0,%1},%2;" : "=f"(lo), "=f"(hi) : "l"(v));
}
static __device__ __forceinline__ u64 fma2(u64 a, u64 b, u64 c) {
    u64 d; asm("fma.rn.f32x2 %0,%1,%2,%3;" : "=l"(d) : "l"(a), "l"(b), "l"(c)); return d;
}
static __device__ __forceinline__ u64 dup2(float w) {
    uint32_t b = __float_as_uint(w);
    return ((u64)b << 32) | (u64)b;
}
static __device__ __forceinline__ float tanha(float v) {
    float r; asm("tanh.approx.f32 %0,%1;" : "=f"(r) : "f"(v)); return r;
}

// ---------- kernel A: per-block partial sums of |x| ----------
__global__ void __launch_bounds__(256) k_a_red(const float4* __restrict__ x, int n4) {
    float s = 0.f;
    for (int i = blockIdx.x * blockDim.x + threadIdx.x; i < n4;
         i += gridDim.x * blockDim.x) {
        float4 v = x[i];
        s += fabsf(v.x) + fabsf(v.y) + fabsf(v.z) + fabsf(v.w);
    }
#pragma unroll
    for (int o = 16; o > 0; o >>= 1) s += __shfl_down_sync(0xffffffffu, s, o);
    __shared__ float ws[8];
    int w = threadIdx.x >> 5, l = threadIdx.x & 31;
    if (l == 0) ws[w] = s;
    __syncthreads();
    if (threadIdx.x == 0) {
        float t = 0.f;
#pragma unroll
        for (int i = 0; i < 8; i++) t += ws[i];
        g_partials[blockIdx.x] = t;
    }
}

// ---------- kernel B: finish reduction + build duplicated tables ----------
__global__ void __launch_bounds__(256) k_prep(
    const float* __restrict__ Wi, const float* __restrict__ bi,
    const float* __restrict__ Wr, const float* __restrict__ Wo,
    const float* __restrict__ bo, const float* __restrict__ tau,
    const float* __restrict__ ta, float invN)
{
    __shared__ float red[256];
    __shared__ float urg_s;
    int t = threadIdx.x;

    float s = 0.f;
    for (int i = t; i < NPART; i += 256) s += g_partials[i];
    red[t] = s;
    __syncthreads();
#pragma unroll
    for (int o = 128; o > 0; o >>= 1) {
        if (t < o) red[t] += red[t + o];
        __syncthreads();
    }
    if (t == 0) urg_s = fmaxf(red[0] * invN, 0.01f);

    u64* gt = (u64*)&g_ctab;
    for (int i = t; i < CTAB_U64; i += 256) gt[i] = 0ull;
    __syncthreads();
    float urg = urg_s;

    for (int i = t; i < DD * HD; i += 256) {
        int k = i / HD, j = i % HD;
        g_ctab.Wi2[k * HJ + j] = dup2(Wi[j * DD + k]);
    }
    for (int i = t; i < HD * HD; i += 256) {
        int k = i / HD, j = i % HD;
        g_ctab.Wr2[k * HJ + j] = dup2(Wr[j * HD + k]);
        g_ctab.Wo2[k * HJ + j] = dup2(Wo[j * HD + k]);
    }
    if (t < HD) {
        g_ctab.bi2[t] = dup2(bi[t]);
        g_ctab.bo2[t] = dup2(bo[t]);
        float td = tau[t] * (1.0f - ta[t]) + ta[t] / urg;
        td = fminf(fmaxf(td, 0.01f), 10.0f);
        g_ctab.bdt2[t] = dup2(0.01f / td);
    }
}

// ---------- kernel C: f32x2 batch-packed, constant weights ----------
__global__ void __launch_bounds__(TPB)
k_main(const float* __restrict__ x, const int* __restrict__ steps_p,
       float* __restrict__ out, float* __restrict__ hout)
{
    __shared__ u64 mst[HD * TPB];       // packed mapped staging [j][tid] (19456 B)

    const int tid = threadIdx.x;
    const size_t row0 = (size_t)blockIdx.x * RPB + tid;
    const float4* xr0 = (const float4*)(x + row0 * DD);
    const float4* xr1 = (const float4*)(x + (row0 + TPB) * DD);

    // ---- phase 1: mapped = x @ Wi^T + bi, packed over the 2 rows ----
    {
        u64 m[HD];
#pragma unroll
        for (int j = 0; j < HD; j++) m[j] = c_tab.bi2[j];
#pragma unroll 4
        for (int q = 0; q < DD / 4; q++) {
            float4 v0 = xr0[q];
            float4 v1 = xr1[q];
            float a0v[4] = {v0.x, v0.y, v0.z, v0.w};
            float a1v[4] = {v1.x, v1.y, v1.z, v1.w};
#pragma unroll
            for (int e = 0; e < 4; e++) {
                const int k = q * 4 + e;
                u64 xd = pk2(a0v[e], a1v[e]);
#pragma unroll
                for (int j = 0; j < HD; j++)
                    m[j] = fma2(xd, c_tab.Wi2[k * HJ + j], m[j]);
            }
        }
#pragma unroll
        for (int j = 0; j < HD; j++) mst[j * TPB + tid] = m[j];
    }
    // each thread reads only its own mst slots below; no block sync needed

    // ---- phase 2: recurrence (packed; no unpack in the matvec) ----
    u64 h[HD];
    const u64 zero2 = 0ull;
    const u64 neg1  = pk2(-1.f, -1.f);
#pragma unroll
    for (int j = 0; j < HD; j++) h[j] = zero2;

    const int steps = *steps_p;
    for (int s = 0; s < steps; s++) {
        u64 a[HD];
#pragma unroll
        for (int j = 0; j < HD; j++) a[j] = mst[j * TPB + tid];
#pragma unroll
        for (int k = 0; k < HD; k++) {
            u64 hk = h[k];                      // already (row0,row1) packed
#pragma unroll
            for (int j = 0; j < HD; j++)
                a[j] = fma2(hk, c_tab.Wr2[k * HJ + j], a[j]);
        }
#pragma unroll
        for (int j = 0; j < HD; j++) {
            float u, v;
            upk2(a[j], u, v);
            u64 act = pk2(tanha(u), tanha(v));
            u64 d = fma2(h[j], neg1, act);      // act - h
            h[j] = fma2(c_tab.bdt2[j], d, h[j]);
        }
    }

    // ---- phase 3: out = h @ Wo^T + bo ----
    u64 o[HD];
#pragma unroll
    for (int j = 0; j < HD; j++) o[j] = c_tab.bo2[j];
#pragma unroll
    for (int k = 0; k < HD; k++) {
        u64 hk = h[k];
#pragma unroll
        for (int j = 0; j < HD; j++)
            o[j] = fma2(hk, c_tab.Wo2[k * HJ + j], o[j]);
    }

    // ---- stage + coalesced stores (reuse mst as float buffer) ----
    __syncthreads();
    float* f = (float*)mst;                     // 4864 floats needed, 4864 avail
#pragma unroll
    for (int j = 0; j < HD; j++) {
        float lo, hi;
        upk2(o[j], lo, hi);
        f[tid * HD + j]         = lo;
        f[(TPB + tid) * HD + j] = hi;
    }
    __syncthreads();
    {
        float4* go = (float4*)(out + (size_t)blockIdx.x * (RPB * HD));
        const float4* f4 = (const float4*)f;
        for (int i = tid; i < RPB * HD / 4; i += TPB) go[i] = f4[i];
    }
    if (hout) {
        __syncthreads();
#pragma unroll
        for (int j = 0; j < HD; j++) {
            float lo, hi;
            upk2(h[j], lo, hi);
            f[tid * HD + j]         = lo;
            f[(TPB + tid) * HD + j] = hi;
        }
        __syncthreads();
        float4* gh = (float4*)(hout + (size_t)blockIdx.x * (RPB * HD));
        const float4* f4 = (const float4*)f;
        for (int i = tid; i < RPB * HD / 4; i += TPB) gh[i] = f4[i];
    }
}

extern "C" void kernel_launch(void* const* d_in, const int* in_sizes, int n_in,
                              void* d_out, int out_size) {
    const float* x   = (const float*)d_in[0];
    const float* Wi  = (const float*)d_in[1];
    const float* bi  = (const float*)d_in[2];
    const float* Wr  = (const float*)d_in[3];
    const float* Wo  = (const float*)d_in[4];
    const float* bo  = (const float*)d_in[5];
    const float* tau = (const float*)d_in[6];
    const float* ta  = (const float*)d_in[7];
    const int* steps = (const int*)d_in[8];

    const int nx = in_sizes[0];
    const int B  = nx / DD;

    float* out = (float*)d_out;
    long long bh = (long long)B * HD;
    float* hout = ((long long)out_size >= 2 * bh) ? (out + bh) : nullptr;

    static void* g_ctab_addr = nullptr;
    if (!g_ctab_addr) cudaGetSymbolAddress(&g_ctab_addr, g_ctab);

    k_a_red<<<NPART, 256>>>((const float4*)x, nx / 4);
    k_prep<<<1, 256>>>(Wi, bi, Wr, Wo, bo, tau, ta, 1.0f / (float)nx);
    cudaMemcpyToSymbolAsync(c_tab, g_ctab_addr, sizeof(CTab), 0,
                            cudaMemcpyDeviceToDevice, 0);
    k_main<<<B / RPB, TPB>>>(x, steps, out, hout);
}